// round 2
// baseline (speedup 1.0000x reference)
#include <cuda_runtime.h>
#include <math.h>

#define Bn   8
#define Hh   128
#define Wd   128
#define Cc   192
#define Gg   6
#define GC   32
#define KK2  9
#define NOFF 108     // G*K2*2
#define NMSK 54      // G*K2
#define M_PIX (Bn*Hh*Wd)   // 131072

// Scratch (device globals — no runtime allocation allowed)
__device__ float g_xproj[(size_t)M_PIX * Cc];
__device__ float g_xd   [(size_t)M_PIX * Cc];
__device__ float g_tmp  [(size_t)M_PIX * Cc];
__device__ float g_off  [(size_t)M_PIX * NOFF];
__device__ float g_msk  [(size_t)M_PIX * NMSK];

// ---------------------------------------------------------------------------
// TF32 tensor-core GEMM: C[M,N] = A[M,K] @ W[K,N] + bias[N]
// BM=128, BN=64, BK=16, 256 threads (8 warps, 4x2), warp tile 32x32.
// SPLIT=true -> tf32x3 (hi/lo error compensation, ~fp32 accuracy).
// ---------------------------------------------------------------------------
__device__ __forceinline__ unsigned f2tf32(float x) {
    unsigned u;
    asm("cvt.rna.tf32.f32 %0, %1;" : "=r"(u) : "f"(x));
    return u;
}

__device__ __forceinline__ void mma_tf32(float* d, const unsigned* a, const unsigned* b) {
    asm volatile(
        "mma.sync.aligned.m16n8k8.row.col.f32.tf32.tf32.f32 "
        "{%0,%1,%2,%3}, {%4,%5,%6,%7}, {%8,%9}, {%0,%1,%2,%3};\n"
        : "+f"(d[0]), "+f"(d[1]), "+f"(d[2]), "+f"(d[3])
        : "r"(a[0]), "r"(a[1]), "r"(a[2]), "r"(a[3]), "r"(b[0]), "r"(b[1]));
}

template<bool SPLIT>
__global__ __launch_bounds__(256) void gemm_tf32(
    const float* __restrict__ A, const float* __restrict__ W,
    const float* __restrict__ bias, float* __restrict__ C,
    int M, int N, int K)
{
    const int BM = 128, BN = 64, BK = 16;
    const int ASTR = BM + 8;   // 136: 8-bank shift per k-row -> conflict-free
    const int BSTR = BN + 8;   // 72
    constexpr int NSP = SPLIT ? 2 : 1;

    __shared__ unsigned As[NSP][BK][ASTR];
    __shared__ unsigned Bs[NSP][BK][BSTR];

    const int bm = blockIdx.y * BM;
    const int bn = blockIdx.x * BN;
    const int tid = threadIdx.x;
    const int wid = tid >> 5;
    const int lane = tid & 31;
    const int gid = lane >> 2;
    const int tig = lane & 3;
    const int wm = (wid & 3) * 32;
    const int wn = (wid >> 2) * 32;

    float acc[2][4][4];
#pragma unroll
    for (int mt = 0; mt < 2; mt++)
#pragma unroll
        for (int nt = 0; nt < 4; nt++)
#pragma unroll
            for (int r = 0; r < 4; r++) acc[mt][nt][r] = 0.f;

    // A tile: 128 rows x 16 k = 512 float4 chunks, 2 per thread
    int a_row[2], a_k[2];
    float4 a_pref[2];
#pragma unroll
    for (int i = 0; i < 2; i++) {
        int ch = tid + i * 256;
        a_row[i] = ch >> 2;
        a_k[i]   = (ch & 3) * 4;
    }
    // B tile: 16 x 64 = 1024 elems, 4 per thread
    int b_kk[4], b_nn[4];
    float b_pref[4];
#pragma unroll
    for (int i = 0; i < 4; i++) {
        int idx = tid + i * 256;
        b_kk[i] = idx >> 6;
        b_nn[i] = idx & 63;
    }

    auto load_gmem = [&](int k0) {
#pragma unroll
        for (int i = 0; i < 2; i++)
            a_pref[i] = *reinterpret_cast<const float4*>(
                &A[(size_t)(bm + a_row[i]) * K + k0 + a_k[i]]);
#pragma unroll
        for (int i = 0; i < 4; i++) {
            int ncol = bn + b_nn[i];
            b_pref[i] = (ncol < N) ? W[(size_t)(k0 + b_kk[i]) * N + ncol] : 0.f;
        }
    };
    auto store_smem = [&]() {
#pragma unroll
        for (int i = 0; i < 2; i++) {
            float v[4] = {a_pref[i].x, a_pref[i].y, a_pref[i].z, a_pref[i].w};
#pragma unroll
            for (int j = 0; j < 4; j++) {
                unsigned hi = f2tf32(v[j]);
                As[0][a_k[i] + j][a_row[i]] = hi;
                if (SPLIT)
                    As[1][a_k[i] + j][a_row[i]] = f2tf32(v[j] - __uint_as_float(hi));
            }
        }
#pragma unroll
        for (int i = 0; i < 4; i++) {
            unsigned hi = f2tf32(b_pref[i]);
            Bs[0][b_kk[i]][b_nn[i]] = hi;
            if (SPLIT)
                Bs[1][b_kk[i]][b_nn[i]] = f2tf32(b_pref[i] - __uint_as_float(hi));
        }
    };

    load_gmem(0);
    store_smem();
    __syncthreads();

    for (int k0 = 0; k0 < K; k0 += BK) {
        bool more = (k0 + BK) < K;
        if (more) load_gmem(k0 + BK);

#pragma unroll
        for (int ks = 0; ks < 2; ks++) {
            const int kb = ks * 8;
            unsigned a_hi[2][4], a_lo[2][4], b_hi[4][2], b_lo[4][2];
#pragma unroll
            for (int mt = 0; mt < 2; mt++) {
                int rb = wm + mt * 16;
                a_hi[mt][0] = As[0][kb + tig    ][rb + gid];
                a_hi[mt][1] = As[0][kb + tig    ][rb + gid + 8];
                a_hi[mt][2] = As[0][kb + tig + 4][rb + gid];
                a_hi[mt][3] = As[0][kb + tig + 4][rb + gid + 8];
                if (SPLIT) {
                    a_lo[mt][0] = As[NSP-1][kb + tig    ][rb + gid];
                    a_lo[mt][1] = As[NSP-1][kb + tig    ][rb + gid + 8];
                    a_lo[mt][2] = As[NSP-1][kb + tig + 4][rb + gid];
                    a_lo[mt][3] = As[NSP-1][kb + tig + 4][rb + gid + 8];
                }
            }
#pragma unroll
            for (int nt = 0; nt < 4; nt++) {
                int col = wn + nt * 8 + gid;
                b_hi[nt][0] = Bs[0][kb + tig    ][col];
                b_hi[nt][1] = Bs[0][kb + tig + 4][col];
                if (SPLIT) {
                    b_lo[nt][0] = Bs[NSP-1][kb + tig    ][col];
                    b_lo[nt][1] = Bs[NSP-1][kb + tig + 4][col];
                }
            }
#pragma unroll
            for (int mt = 0; mt < 2; mt++)
#pragma unroll
                for (int nt = 0; nt < 4; nt++) {
                    mma_tf32(acc[mt][nt], a_hi[mt], b_hi[nt]);
                    if (SPLIT) {
                        mma_tf32(acc[mt][nt], a_hi[mt], b_lo[nt]);
                        mma_tf32(acc[mt][nt], a_lo[mt], b_hi[nt]);
                    }
                }
        }
        __syncthreads();
        if (more) {
            store_smem();
            __syncthreads();
        }
    }

    // Epilogue
#pragma unroll
    for (int mt = 0; mt < 2; mt++) {
        int row0 = bm + wm + mt * 16 + gid;
#pragma unroll
        for (int nt = 0; nt < 4; nt++) {
            int col0 = bn + wn + nt * 8 + 2 * tig;
            if (col0 < N) {
                C[(size_t)row0 * N + col0]       = acc[mt][nt][0] + bias[col0];
                C[(size_t)(row0 + 8) * N + col0] = acc[mt][nt][2] + bias[col0];
            }
            if (col0 + 1 < N) {
                C[(size_t)row0 * N + col0 + 1]       = acc[mt][nt][1] + bias[col0 + 1];
                C[(size_t)(row0 + 8) * N + col0 + 1] = acc[mt][nt][3] + bias[col0 + 1];
            }
        }
    }
}

// ---------------------------------------------------------------------------
// Depthwise 3x3 'SAME' conv + bias + SiLU, float4-vectorized (C = 48 float4).
// ---------------------------------------------------------------------------
__global__ __launch_bounds__(256) void dw_silu(
    const float4* __restrict__ x, const float4* __restrict__ wdw,
    const float4* __restrict__ bdw, float4* __restrict__ out)
{
    const int C4 = Cc / 4;  // 48
    size_t idx = (size_t)blockIdx.x * blockDim.x + threadIdx.x;
    if (idx >= (size_t)M_PIX * C4) return;
    int c4 = (int)(idx % C4);
    int p = (int)(idx / C4);
    int w = p % Wd;
    int h = (p / Wd) % Hh;
    int b = p / (Wd * Hh);

    float4 acc = bdw[c4];
#pragma unroll
    for (int ky = 0; ky < 3; ky++) {
        int hy = h + ky - 1;
        if (hy < 0 || hy >= Hh) continue;
#pragma unroll
        for (int kx = 0; kx < 3; kx++) {
            int wx = w + kx - 1;
            if (wx < 0 || wx >= Wd) continue;
            float4 v  = x[((size_t)(b * Hh + hy) * Wd + wx) * C4 + c4];
            float4 wt = wdw[(ky * 3 + kx) * C4 + c4];
            acc.x = fmaf(v.x, wt.x, acc.x);
            acc.y = fmaf(v.y, wt.y, acc.y);
            acc.z = fmaf(v.z, wt.z, acc.z);
            acc.w = fmaf(v.w, wt.w, acc.w);
        }
    }
    acc.x = acc.x / (1.f + expf(-acc.x));
    acc.y = acc.y / (1.f + expf(-acc.y));
    acc.z = acc.z / (1.f + expf(-acc.z));
    acc.w = acc.w / (1.f + expf(-acc.w));
    out[idx] = acc;
}

// ---------------------------------------------------------------------------
// Fused softmax + deformable bilinear sampling (unchanged this round).
// ---------------------------------------------------------------------------
__global__ __launch_bounds__(192) void deform_sample(
    const float* __restrict__ xproj, const float* __restrict__ off,
    const float* __restrict__ msk, float* __restrict__ out)
{
    const int pix = blockIdx.x;
    const int tid = threadIdx.x;

    __shared__ float s_off[NOFF];
    __shared__ float s_m[NMSK];
    __shared__ float s_ph[NMSK], s_pw[NMSK], s_a[NMSK];

    if (tid < NOFF) s_off[tid] = off[(size_t)pix * NOFF + tid];
    if (tid >= 128 && tid < 128 + NMSK) s_m[tid - 128] = msk[(size_t)pix * NMSK + (tid - 128)];
    __syncthreads();

    const int w = pix % Wd;
    const int h = (pix / Wd) % Hh;
    const int b = pix / (Wd * Hh);

    if (tid < NMSK) {
        int k = tid % KK2;
        float ri = (float)(k / 3 - 1);
        float rj = (float)(k % 3 - 1);
        float ph = (float)h + ri + s_off[tid * 2 + 0] * 0.1f;
        float pw = (float)w + rj + s_off[tid * 2 + 1] * 0.1f;
        s_ph[tid] = fminf(fmaxf(ph, 0.f), (float)(Hh - 1));
        s_pw[tid] = fminf(fmaxf(pw, 0.f), (float)(Wd - 1));
    }
    if (tid >= 64 && tid < 64 + Gg) {
        int g = tid - 64;
        float mx = -1e30f;
#pragma unroll
        for (int k = 0; k < KK2; k++) mx = fmaxf(mx, s_m[g * KK2 + k]);
        float e[KK2], sum = 0.f;
#pragma unroll
        for (int k = 0; k < KK2; k++) { e[k] = expf(s_m[g * KK2 + k] - mx); sum += e[k]; }
        float inv = 1.f / sum;
#pragma unroll
        for (int k = 0; k < KK2; k++) s_a[g * KK2 + k] = e[k] * inv;
    }
    __syncthreads();

    const int g = tid >> 5;
    const int cc = tid & 31;
    const float* xb = xproj + (size_t)b * Hh * Wd * Cc + g * GC + cc;

    float acc = 0.f;
#pragma unroll
    for (int k = 0; k < KK2; k++) {
        float ph = s_ph[g * KK2 + k];
        float pw = s_pw[g * KK2 + k];
        float a  = s_a [g * KK2 + k];
        int hf = (int)ph;
        int wf = (int)pw;
        int hc = min(hf + 1, Hh - 1);
        int wc = min(wf + 1, Wd - 1);
        float hw = ph - (float)hf;
        float ww = pw - (float)wf;
        float v00 = xb[((size_t)hf * Wd + wf) * Cc];
        float v01 = xb[((size_t)hf * Wd + wc) * Cc];
        float v10 = xb[((size_t)hc * Wd + wf) * Cc];
        float v11 = xb[((size_t)hc * Wd + wc) * Cc];
        float top = fmaf(ww, v01 - v00, v00);
        float bot = fmaf(ww, v11 - v10, v10);
        acc = fmaf(a, fmaf(hw, bot - top, top), acc);
    }
    out[(size_t)pix * Cc + tid] = acc;
}

// ---------------------------------------------------------------------------
// Launch
// ---------------------------------------------------------------------------
extern "C" void kernel_launch(void* const* d_in, const int* in_sizes, int n_in,
                              void* d_out, int out_size)
{
    const float* x      = (const float*)d_in[0];
    const float* w_in   = (const float*)d_in[1];
    const float* b_in   = (const float*)d_in[2];
    const float* w_dw   = (const float*)d_in[3];
    const float* b_dw   = (const float*)d_in[4];
    const float* w_pw   = (const float*)d_in[5];
    const float* b_pw   = (const float*)d_in[6];
    const float* w_off  = (const float*)d_in[7];
    const float* b_off  = (const float*)d_in[8];
    const float* w_mask = (const float*)d_in[9];
    const float* b_mask = (const float*)d_in[10];
    const float* w_out  = (const float*)d_in[11];
    const float* b_out  = (const float*)d_in[12];
    float* out = (float*)d_out;

    float *xproj, *xd, *tmp, *offp, *mskp;
    cudaGetSymbolAddress((void**)&xproj, g_xproj);
    cudaGetSymbolAddress((void**)&xd,    g_xd);
    cudaGetSymbolAddress((void**)&tmp,   g_tmp);
    cudaGetSymbolAddress((void**)&offp,  g_off);
    cudaGetSymbolAddress((void**)&mskp,  g_msk);

    const int M = M_PIX, K = Cc;
    dim3 blk(256);
    dim3 grid_c((Cc + 63) / 64, M / 128);
    dim3 grid_o((NOFF + 63) / 64, M / 128);
    dim3 grid_m((NMSK + 63) / 64, M / 128);

    // 1. x_proj = x @ w_in + b_in  (precision-critical: tf32x3)
    gemm_tf32<true><<<grid_c, blk>>>(x, w_in, b_in, xproj, M, Cc, K);
    // 2. depthwise 3x3 + SiLU
    {
        size_t n = (size_t)M_PIX * (Cc / 4);
        dw_silu<<<(unsigned)((n + 255) / 256), 256>>>(
            (const float4*)x, (const float4*)w_dw, (const float4*)b_dw, (float4*)tmp);
    }
    // 3. xd = dw_out @ w_pw + b_pw  (feeds only sampling weights: plain tf32)
    gemm_tf32<false><<<grid_c, blk>>>(tmp, w_pw, b_pw, xd, M, Cc, K);
    // 4. offsets = xd @ w_off + b_off  (damped by 0.1 scale: plain tf32)
    gemm_tf32<false><<<grid_o, blk>>>(xd, w_off, b_off, offp, M, NOFF, K);
    // 5. mask logits = xd @ w_mask + b_mask  (softmax-damped: plain tf32)
    gemm_tf32<false><<<grid_m, blk>>>(xd, w_mask, b_mask, mskp, M, NMSK, K);
    // 6. softmax + deformable sampling -> tmp (reused)
    deform_sample<<<M_PIX, 192>>>(xproj, offp, mskp, tmp);
    // 7. out = sampled @ w_out + b_out  (precision-critical: tf32x3)
    gemm_tf32<true><<<grid_c, blk>>>(tmp, w_out, b_out, out, M, Cc, K);
}

// round 3
// speedup vs baseline: 1.9877x; 1.9877x over previous
#include <cuda_runtime.h>
#include <math.h>

#define Bn   8
#define Hh   128
#define Wd   128
#define Cc   192
#define Gg   6
#define GC   32
#define KK2  9
#define NFUS 162     // 108 offsets + 54 mask logits
#define M_PIX (Bn*Hh*Wd)   // 131072

// Scratch (device globals — no runtime allocation allowed)
__device__ float g_xproj [(size_t)M_PIX * Cc];
__device__ float g_tmp   [(size_t)M_PIX * Cc];     // dwout, later sampled output
__device__ float g_offmsk[(size_t)M_PIX * NFUS];
__device__ float g_wf    [Cc * NFUS];
__device__ float g_bf    [NFUS];

// ---------------------------------------------------------------------------
// TF32 helpers
// ---------------------------------------------------------------------------
__device__ __forceinline__ unsigned f2tf32(float x) {
    unsigned u;
    asm("cvt.rna.tf32.f32 %0, %1;" : "=r"(u) : "f"(x));
    return u;
}
__device__ __forceinline__ void mma_tf32(float* d, const unsigned* a, unsigned b0, unsigned b1) {
    asm volatile(
        "mma.sync.aligned.m16n8k8.row.col.f32.tf32.tf32.f32 "
        "{%0,%1,%2,%3}, {%4,%5,%6,%7}, {%8,%9}, {%0,%1,%2,%3};\n"
        : "+f"(d[0]), "+f"(d[1]), "+f"(d[2]), "+f"(d[3])
        : "r"(a[0]), "r"(a[1]), "r"(a[2]), "r"(a[3]), "r"(b0), "r"(b1));
}

// ---------------------------------------------------------------------------
// TF32 tensor-core GEMM with fragment-major (permuted) smem layouts.
// C[M,N] = A[M,K] @ W[K,N] + bias[N].
// BM=128, BN=64, BK=16, 256 threads (8 warps: 4 along M x 2 along N),
// warp tile 32x32. Fragments load as single LDS.128, conflict-free.
// SPLIT=true -> tf32x3 (hi/lo compensation).
// A layout: As[buf][s][ks][mb(8)][lane(32)][reg(4)]
// B layout: Bs[buf][s][ks][ wn2*288 + tig*72 + pr*32 + gid*4 + j ]  (576/ks)
// ---------------------------------------------------------------------------
template<bool SPLIT>
__global__ __launch_bounds__(256) void gemm_tf32(
    const float* __restrict__ A, const float* __restrict__ W,
    const float* __restrict__ bias, float* __restrict__ C,
    int M, int N, int K)
{
    constexpr int NSP = SPLIT ? 2 : 1;
    const int BK = 16;

    __shared__ unsigned As[2][NSP][2][8][32][4];   // 2KB *NSP*2 buf *... (8KB/s/buf)
    __shared__ unsigned Bs[2][NSP][2][576];

    const int bm = blockIdx.y * 128;
    const int bn = blockIdx.x * 64;
    const int tid = threadIdx.x;
    const int wid = tid >> 5;
    const int lane = tid & 31;
    const int gid = lane >> 2;
    const int tig = lane & 3;
    const int wm = (wid & 3) * 32;
    const int wn2 = wid >> 2;            // 0 or 1 (warp col tile of 32)

    float acc[2][4][4];
#pragma unroll
    for (int mt = 0; mt < 2; mt++)
#pragma unroll
        for (int nt = 0; nt < 4; nt++)
#pragma unroll
            for (int r = 0; r < 4; r++) acc[mt][nt][r] = 0.f;

    // ---- global load assignments ----
    // A: 128 rows x 16 k = 512 float4, 2 per thread
    int a_row[2], a_kq[2];
    float4 a_pref[2];
#pragma unroll
    for (int i = 0; i < 2; i++) {
        int ch = tid + i * 256;
        a_row[i] = ch >> 2;
        a_kq[i]  = (ch & 3) * 4;
    }
    // B: 16 x 64 = 1024 elems, 4 per thread
    int b_kk[4], b_nn[4];
    float b_pref[4];
#pragma unroll
    for (int i = 0; i < 4; i++) {
        int idx = tid + i * 256;
        b_kk[i] = idx >> 6;
        b_nn[i] = idx & 63;
    }

    auto load_gmem = [&](int k0) {
#pragma unroll
        for (int i = 0; i < 2; i++)
            a_pref[i] = *reinterpret_cast<const float4*>(
                &A[(size_t)(bm + a_row[i]) * K + k0 + a_kq[i]]);
#pragma unroll
        for (int i = 0; i < 4; i++) {
            int ncol = bn + b_nn[i];
            b_pref[i] = (ncol < N) ? W[(size_t)(k0 + b_kk[i]) * N + ncol] : 0.f;
        }
    };

    auto store_smem = [&](int buf) {
        // A: element (r, kk=a_kq+j): ks=kk>>3, mb=r>>4, gid'=r&7, half=(r>>3)&1,
        //    tig'=j, khalf=(kk>>2)&1, lane'=gid'*4+j, reg=half+2*khalf
#pragma unroll
        for (int i = 0; i < 2; i++) {
            const int r = a_row[i];
            const int ks = a_kq[i] >> 3;
            const int khalf = (a_kq[i] >> 2) & 1;
            const int mb = r >> 4;
            const int gp = r & 7;
            const int half = (r >> 3) & 1;
            const int reg = half + 2 * khalf;
            float v[4] = {a_pref[i].x, a_pref[i].y, a_pref[i].z, a_pref[i].w};
#pragma unroll
            for (int j = 0; j < 4; j++) {
                unsigned hi = f2tf32(v[j]);
                As[buf][0][ks][mb][gp * 4 + j][reg] = hi;
                if (SPLIT)
                    As[buf][NSP-1][ks][mb][gp * 4 + j][reg] = f2tf32(v[j] - __uint_as_float(hi));
            }
        }
        // B: element (kk, c): ks=kk>>3, t=kk&3, kh=(kk>>2)&1; w2=c>>5, cc=c&31,
        //    g=cc&7, nt=cc>>3, pr=nt>>1, j=kh+2*(nt&1)
#pragma unroll
        for (int i = 0; i < 4; i++) {
            const int kk = b_kk[i], c = b_nn[i];
            const int ks = kk >> 3, t = kk & 3, kh = (kk >> 2) & 1;
            const int w2 = c >> 5, cc = c & 31;
            const int g = cc & 7, nt = cc >> 3;
            const int idx = w2 * 288 + t * 72 + (nt >> 1) * 32 + g * 4 + (kh + 2 * (nt & 1));
            unsigned hi = f2tf32(b_pref[i]);
            Bs[buf][0][ks][idx] = hi;
            if (SPLIT)
                Bs[buf][NSP-1][ks][idx] = f2tf32(b_pref[i] - __uint_as_float(hi));
        }
    };

    load_gmem(0);
    store_smem(0);
    __syncthreads();

    int buf = 0;
    const int mb0 = wm >> 4;

    for (int k0 = 0; k0 < K; k0 += BK) {
        const bool more = (k0 + BK) < K;
        if (more) load_gmem(k0 + BK);

#pragma unroll
        for (int ks = 0; ks < 2; ks++) {
            unsigned afr[NSP][2][4];
            uint4 bfr[NSP][2];
#pragma unroll
            for (int s = 0; s < NSP; s++) {
#pragma unroll
                for (int mt = 0; mt < 2; mt++) {
                    uint4 av = *reinterpret_cast<const uint4*>(&As[buf][s][ks][mb0 + mt][lane][0]);
                    afr[s][mt][0] = av.x; afr[s][mt][1] = av.y;
                    afr[s][mt][2] = av.z; afr[s][mt][3] = av.w;
                }
#pragma unroll
                for (int pr = 0; pr < 2; pr++)
                    bfr[s][pr] = *reinterpret_cast<const uint4*>(
                        &Bs[buf][s][ks][wn2 * 288 + tig * 72 + pr * 32 + gid * 4]);
            }
#pragma unroll
            for (int mt = 0; mt < 2; mt++)
#pragma unroll
                for (int pr = 0; pr < 2; pr++) {
                    mma_tf32(acc[mt][2*pr],   afr[0][mt], bfr[0][pr].x, bfr[0][pr].y);
                    mma_tf32(acc[mt][2*pr+1], afr[0][mt], bfr[0][pr].z, bfr[0][pr].w);
                    if (SPLIT) {
                        mma_tf32(acc[mt][2*pr],   afr[0][mt], bfr[NSP-1][pr].x, bfr[NSP-1][pr].y);
                        mma_tf32(acc[mt][2*pr+1], afr[0][mt], bfr[NSP-1][pr].z, bfr[NSP-1][pr].w);
                        mma_tf32(acc[mt][2*pr],   afr[NSP-1][mt], bfr[0][pr].x, bfr[0][pr].y);
                        mma_tf32(acc[mt][2*pr+1], afr[NSP-1][mt], bfr[0][pr].z, bfr[0][pr].w);
                    }
                }
        }
        if (more) store_smem(buf ^ 1);
        __syncthreads();
        buf ^= 1;
    }

    // Epilogue
#pragma unroll
    for (int mt = 0; mt < 2; mt++) {
        int row0 = bm + wm + mt * 16 + gid;
#pragma unroll
        for (int nt = 0; nt < 4; nt++) {
            int col0 = bn + wn2 * 32 + nt * 8 + 2 * tig;
            if (col0 < N) {
                C[(size_t)row0 * N + col0]       = acc[mt][nt][0] + bias[col0];
                C[(size_t)(row0 + 8) * N + col0] = acc[mt][nt][2] + bias[col0];
            }
            if (col0 + 1 < N) {
                C[(size_t)row0 * N + col0 + 1]       = acc[mt][nt][1] + bias[col0 + 1];
                C[(size_t)(row0 + 8) * N + col0 + 1] = acc[mt][nt][3] + bias[col0 + 1];
            }
        }
    }
}

// ---------------------------------------------------------------------------
// Weight fusion: W_f[i][n] = sum_o w_pw[i][o] * Wcat[o][n]  (exact fp32)
// Wcat = [w_off | w_mask] along n.  bias_f[n] = b_cat[n] + sum_o b_pw[o]*Wcat[o][n]
// ---------------------------------------------------------------------------
__global__ void fuse_weights(const float* __restrict__ wpw,
                             const float* __restrict__ woff,
                             const float* __restrict__ wmask,
                             float* __restrict__ wf)
{
    int i = blockIdx.x;
    int n = threadIdx.x;
    if (n >= NFUS) return;
    const float* wrow = wpw + (size_t)i * Cc;
    float acc = 0.f;
    if (n < 108) {
        for (int o = 0; o < Cc; o++) acc = fmaf(wrow[o], woff[(size_t)o * 108 + n], acc);
    } else {
        int n2 = n - 108;
        for (int o = 0; o < Cc; o++) acc = fmaf(wrow[o], wmask[(size_t)o * 54 + n2], acc);
    }
    wf[(size_t)i * NFUS + n] = acc;
}

__global__ void fuse_bias(const float* __restrict__ bpw,
                          const float* __restrict__ woff,
                          const float* __restrict__ wmask,
                          const float* __restrict__ boff,
                          const float* __restrict__ bmask,
                          float* __restrict__ bf)
{
    int n = threadIdx.x;
    if (n >= NFUS) return;
    float acc = (n < 108) ? boff[n] : bmask[n - 108];
    if (n < 108) {
        for (int o = 0; o < Cc; o++) acc = fmaf(bpw[o], woff[(size_t)o * 108 + n], acc);
    } else {
        int n2 = n - 108;
        for (int o = 0; o < Cc; o++) acc = fmaf(bpw[o], wmask[(size_t)o * 54 + n2], acc);
    }
    bf[n] = acc;
}

// ---------------------------------------------------------------------------
// Depthwise 3x3 'SAME' conv + bias + SiLU, float4-vectorized.
// ---------------------------------------------------------------------------
__global__ __launch_bounds__(256) void dw_silu(
    const float4* __restrict__ x, const float4* __restrict__ wdw,
    const float4* __restrict__ bdw, float4* __restrict__ out)
{
    const int C4 = Cc / 4;  // 48
    size_t idx = (size_t)blockIdx.x * blockDim.x + threadIdx.x;
    if (idx >= (size_t)M_PIX * C4) return;
    int c4 = (int)(idx % C4);
    int p = (int)(idx / C4);
    int w = p % Wd;
    int h = (p / Wd) % Hh;
    int b = p / (Wd * Hh);

    float4 acc = bdw[c4];
#pragma unroll
    for (int ky = 0; ky < 3; ky++) {
        int hy = h + ky - 1;
        if (hy < 0 || hy >= Hh) continue;
#pragma unroll
        for (int kx = 0; kx < 3; kx++) {
            int wx = w + kx - 1;
            if (wx < 0 || wx >= Wd) continue;
            float4 v  = x[((size_t)(b * Hh + hy) * Wd + wx) * C4 + c4];
            float4 wt = wdw[(ky * 3 + kx) * C4 + c4];
            acc.x = fmaf(v.x, wt.x, acc.x);
            acc.y = fmaf(v.y, wt.y, acc.y);
            acc.z = fmaf(v.z, wt.z, acc.z);
            acc.w = fmaf(v.w, wt.w, acc.w);
        }
    }
    acc.x = acc.x / (1.f + expf(-acc.x));
    acc.y = acc.y / (1.f + expf(-acc.y));
    acc.z = acc.z / (1.f + expf(-acc.z));
    acc.w = acc.w / (1.f + expf(-acc.w));
    out[idx] = acc;
}

// ---------------------------------------------------------------------------
// Tiled deformable sampling + softmax.
// Block = (8x8 pixel tile, one group). Stages 13x13x32 window of x_proj into
// smem ([cell][ch] layout: lane==bank, conflict-free), computes softmax per
// pixel, then 8 warps x (4 passes x 2 pixels/warp) sample from smem.
// Valid while |offset| < 1 (offsets here are ~0.01).
// ---------------------------------------------------------------------------
__global__ __launch_bounds__(256) void deform_tile(
    const float* __restrict__ xproj, const float* __restrict__ offmsk,
    float* __restrict__ out)
{
    const int tile = blockIdx.x;           // 0..2047
    const int g = blockIdx.y;              // 0..5
    const int tid = threadIdx.x;

    const int b  = tile >> 8;
    const int ty = (tile >> 4) & 15;
    const int tx = tile & 15;
    const int h0 = ty * 8, w0 = tx * 8;

    __shared__ float2 xs[13 * 13 * 16];    // [cell][ch2], 21.6KB
    __shared__ float s_ph[64][KK2], s_pw[64][KK2], s_a[64][KK2];

    // Stage window (rows/cols clamped to image -> border duplication handles edges)
    for (int idx = tid; idx < 13 * 13 * 8; idx += 256) {
        int cell = idx >> 3;
        int c4 = idx & 7;
        int hi = cell / 13, wi = cell % 13;
        int row = min(max(h0 - 2 + hi, 0), Hh - 1);
        int col = min(max(w0 - 2 + wi, 0), Wd - 1);
        float4 v = *reinterpret_cast<const float4*>(
            &xproj[(((size_t)(b * Hh + row)) * Wd + col) * Cc + g * GC + c4 * 4]);
        xs[cell * 16 + c4 * 2]     = make_float2(v.x, v.y);
        xs[cell * 16 + c4 * 2 + 1] = make_float2(v.z, v.w);
    }

    // Meta: positions + softmax per pixel
    if (tid < 64) {
        int py = tid >> 3, px = tid & 7;
        int h = h0 + py, w = w0 + px;
        const float* om = offmsk + (((size_t)(b * Hh + h)) * Wd + w) * NFUS;
        float m[KK2], mx = -1e30f;
#pragma unroll
        for (int k = 0; k < KK2; k++) { m[k] = om[108 + g * KK2 + k]; mx = fmaxf(mx, m[k]); }
        float sum = 0.f;
#pragma unroll
        for (int k = 0; k < KK2; k++) { m[k] = expf(m[k] - mx); sum += m[k]; }
        float inv = 1.f / sum;
#pragma unroll
        for (int k = 0; k < KK2; k++) {
            float ph = (float)h + (float)(k / 3 - 1) + om[g * 18 + 2 * k]     * 0.1f;
            float pw = (float)w + (float)(k % 3 - 1) + om[g * 18 + 2 * k + 1] * 0.1f;
            s_ph[tid][k] = fminf(fmaxf(ph, 0.f), (float)(Hh - 1));
            s_pw[tid][k] = fminf(fmaxf(pw, 0.f), (float)(Wd - 1));
            s_a[tid][k] = m[k] * inv;
        }
    }
    __syncthreads();

    const int wid = tid >> 5;
    const int lane = tid & 31;
    const int half = lane >> 4;       // which of 2 pixels this half-warp handles
    const int ch = lane & 15;         // channel pair index (2 channels)

#pragma unroll
    for (int pass = 0; pass < 4; pass++) {
        int p = wid * 8 + pass * 2 + half;
        float2 acc = make_float2(0.f, 0.f);
#pragma unroll
        for (int k = 0; k < KK2; k++) {
            float ph = s_ph[p][k];
            float pw = s_pw[p][k];
            float a  = s_a [p][k];
            int hf = (int)ph;
            int wf = (int)pw;
            float fh = ph - (float)hf;
            float fw = pw - (float)wf;
            int hl = min(max(hf - (h0 - 2), 0), 11);
            int wl = min(max(wf - (w0 - 2), 0), 11);
            int c00 = (hl * 13 + wl) * 16 + ch;
            float2 v00 = xs[c00];
            float2 v01 = xs[c00 + 16];
            float2 v10 = xs[c00 + 13 * 16];
            float2 v11 = xs[c00 + 13 * 16 + 16];
            float tx0 = fmaf(fw, v01.x - v00.x, v00.x);
            float bx0 = fmaf(fw, v11.x - v10.x, v10.x);
            float ty0 = fmaf(fw, v01.y - v00.y, v00.y);
            float by0 = fmaf(fw, v11.y - v10.y, v10.y);
            acc.x = fmaf(a, fmaf(fh, bx0 - tx0, tx0), acc.x);
            acc.y = fmaf(a, fmaf(fh, by0 - ty0, ty0), acc.y);
        }
        int h = h0 + (p >> 3), w = w0 + (p & 7);
        *reinterpret_cast<float2*>(
            &out[(((size_t)(b * Hh + h)) * Wd + w) * Cc + g * GC + ch * 2]) = acc;
    }
}

// ---------------------------------------------------------------------------
// Launch
// ---------------------------------------------------------------------------
extern "C" void kernel_launch(void* const* d_in, const int* in_sizes, int n_in,
                              void* d_out, int out_size)
{
    const float* x      = (const float*)d_in[0];
    const float* w_in   = (const float*)d_in[1];
    const float* b_in   = (const float*)d_in[2];
    const float* w_dw   = (const float*)d_in[3];
    const float* b_dw   = (const float*)d_in[4];
    const float* w_pw   = (const float*)d_in[5];
    const float* b_pw   = (const float*)d_in[6];
    const float* w_off  = (const float*)d_in[7];
    const float* b_off  = (const float*)d_in[8];
    const float* w_mask = (const float*)d_in[9];
    const float* b_mask = (const float*)d_in[10];
    const float* w_out  = (const float*)d_in[11];
    const float* b_out  = (const float*)d_in[12];
    float* out = (float*)d_out;

    float *xproj, *tmp, *offmsk, *wf, *bf;
    cudaGetSymbolAddress((void**)&xproj,  g_xproj);
    cudaGetSymbolAddress((void**)&tmp,    g_tmp);
    cudaGetSymbolAddress((void**)&offmsk, g_offmsk);
    cudaGetSymbolAddress((void**)&wf,     g_wf);
    cudaGetSymbolAddress((void**)&bf,     g_bf);

    const int M = M_PIX, K = Cc;
    dim3 blk(256);
    dim3 grid_c(3, M / 128);   // N=192
    dim3 grid_f(3, M / 128);   // N=162 -> 3 tiles of 64

    // 0. fold pw into offset/mask projections (exact fp32, tiny)
    fuse_weights<<<Cc, 192>>>(w_pw, w_off, w_mask, wf);
    fuse_bias<<<1, 192>>>(b_pw, w_off, w_mask, b_off, b_mask, bf);
    // 1. x_proj = x @ w_in + b_in  (tf32x3)
    gemm_tf32<true><<<grid_c, blk>>>(x, w_in, b_in, xproj, M, Cc, K);
    // 2. depthwise 3x3 + SiLU -> tmp
    {
        size_t n = (size_t)M_PIX * (Cc / 4);
        dw_silu<<<(unsigned)((n + 255) / 256), 256>>>(
            (const float4*)x, (const float4*)w_dw, (const float4*)b_dw, (float4*)tmp);
    }
    // 3. [offsets|mask] = dwout @ W_f + b_f  (plain tf32, N=162)
    gemm_tf32<false><<<grid_f, blk>>>(tmp, wf, bf, offmsk, M, NFUS, K);
    // 4. tiled softmax + deformable sampling -> tmp (reused)
    deform_tile<<<dim3(2048, Gg), 256>>>(xproj, offmsk, tmp);
    // 5. out = sampled @ w_out + b_out  (tf32x3)
    gemm_tf32<true><<<grid_c, blk>>>(tmp, w_out, b_out, out, M, Cc, K);
}

// round 4
// speedup vs baseline: 3.0391x; 1.5289x over previous
#include <cuda_runtime.h>
#include <cuda_bf16.h>
#include <math.h>

#define Bn   8
#define Hh   128
#define Wd   128
#define Cc   192
#define Gg   6
#define GC   32
#define KK2  9
#define NFUS 162     // 108 offsets + 54 mask logits
#define M_PIX (Bn*Hh*Wd)   // 131072

// Scratch (device globals — no runtime allocation allowed)
__device__ float g_xproj [(size_t)M_PIX * Cc];
__device__ float g_tmp   [(size_t)M_PIX * Cc];     // dwout, later sampled output
__device__ float g_offmsk[(size_t)M_PIX * NFUS];
__device__ float g_wf    [Cc * NFUS];
__device__ float g_bf    [NFUS];

// ---------------------------------------------------------------------------
// bf16 helpers
// ---------------------------------------------------------------------------
__device__ __forceinline__ unsigned bf16pair(float a, float b) {
    __nv_bfloat162 t = __floats2bfloat162_rn(a, b);   // a -> low half (even k)
    return *reinterpret_cast<unsigned*>(&t);
}
__device__ __forceinline__ void mma_bf16(float* d, const unsigned* a, unsigned b0, unsigned b1) {
    asm volatile(
        "mma.sync.aligned.m16n8k16.row.col.f32.bf16.bf16.f32 "
        "{%0,%1,%2,%3}, {%4,%5,%6,%7}, {%8,%9}, {%0,%1,%2,%3};\n"
        : "+f"(d[0]), "+f"(d[1]), "+f"(d[2]), "+f"(d[3])
        : "r"(a[0]), "r"(a[1]), "r"(a[2]), "r"(a[3]), "r"(b0), "r"(b1));
}

// ---------------------------------------------------------------------------
// bf16 tensor-core GEMM, fragment-major smem, C = A@W + bias.
// BM=128, BN=64, BK=16 (one m16n8k16 K-step per tile), 256 threads,
// 8 warps (4 along M x 2 along N), warp tile 32x32.
// SPLIT=true -> bf16 hi/lo 3-term compensation (~16-bit mantissa).
// A layout: As[buf][s][mb(8)][lane(32)][reg(4)]  (uint4 per fragment)
// B layout: Bs[buf][s][wn2(2)][tig*72 + pr*32 + gid*4 + ntl*2 + which]
// ---------------------------------------------------------------------------
template<bool SPLIT>
__global__ __launch_bounds__(256) void gemm_bf16(
    const float* __restrict__ A, const float* __restrict__ W,
    const float* __restrict__ bias, float* __restrict__ C,
    int M, int N, int K)
{
    constexpr int NSP = SPLIT ? 2 : 1;
    const int BK = 16;

    __shared__ __align__(16) unsigned As[2][NSP][8][32][4];
    __shared__ __align__(16) unsigned Bs[2][NSP][2][288];

    const int bm = blockIdx.y * 128;
    const int bn = blockIdx.x * 64;
    const int tid = threadIdx.x;
    const int wid = tid >> 5;
    const int lane = tid & 31;
    const int gid = lane >> 2;
    const int tig = lane & 3;
    const int wm = (wid & 3) * 32;
    const int wn2 = wid >> 2;

    float acc[2][4][4];
#pragma unroll
    for (int mt = 0; mt < 2; mt++)
#pragma unroll
        for (int nt = 0; nt < 4; nt++)
#pragma unroll
            for (int r = 0; r < 4; r++) acc[mt][nt][r] = 0.f;

    // A: 128 rows x 16 k = 512 float4 chunks, 2 per thread
    int a_row[2], a_kq[2];
    float4 a_pref[2];
#pragma unroll
    for (int i = 0; i < 2; i++) {
        int ch = tid + i * 256;
        a_row[i] = ch >> 2;
        a_kq[i]  = (ch & 3) * 4;
    }
    // B: 16 x 64 = 1024 elems, 4 per thread
    int b_kk[4], b_nn[4];
    float b_pref[4];
#pragma unroll
    for (int i = 0; i < 4; i++) {
        int idx = tid + i * 256;
        b_kk[i] = idx >> 6;
        b_nn[i] = idx & 63;
    }

    auto load_gmem = [&](int k0) {
#pragma unroll
        for (int i = 0; i < 2; i++)
            a_pref[i] = *reinterpret_cast<const float4*>(
                &A[(size_t)(bm + a_row[i]) * K + k0 + a_kq[i]]);
#pragma unroll
        for (int i = 0; i < 4; i++) {
            int ncol = bn + b_nn[i];
            b_pref[i] = (ncol < N) ? W[(size_t)(k0 + b_kk[i]) * N + ncol] : 0.f;
        }
    };

    auto store_smem = [&](int buf) {
        // ---- A ----
#pragma unroll
        for (int i = 0; i < 2; i++) {
            const int r = a_row[i];
            const int mb = r >> 4;
            const int rl = r & 15;
            const int gp = rl & 7;
            const int half = rl >> 3;
            const int khalf = a_kq[i] >> 3;           // both pairs share khalf
            float v[4] = {a_pref[i].x, a_pref[i].y, a_pref[i].z, a_pref[i].w};
#pragma unroll
            for (int jp = 0; jp < 2; jp++) {
                int k = a_kq[i] + 2 * jp;
                int tigw = (k >> 1) & 3;
                int reg = half + 2 * khalf;
                float v0 = v[2 * jp], v1 = v[2 * jp + 1];
                unsigned hi = bf16pair(v0, v1);
                As[buf][0][mb][gp * 4 + tigw][reg] = hi;
                if (SPLIT) {
                    __nv_bfloat162 h2 = *reinterpret_cast<__nv_bfloat162*>(&hi);
                    float lo0 = v0 - __bfloat162float(h2.x);
                    float lo1 = v1 - __bfloat162float(h2.y);
                    As[buf][NSP-1][mb][gp * 4 + tigw][reg] = bf16pair(lo0, lo1);
                }
            }
        }
        // ---- B ---- (16-bit stores; k-pair halves come from different threads)
#pragma unroll
        for (int i = 0; i < 4; i++) {
            const int kk = b_kk[i], c = b_nn[i];
            const int wn = c >> 5, cl = c & 31;
            const int nt = cl >> 3, gd = cl & 7;
            const int pr = nt >> 1, ntl = nt & 1;
            const int tigw = (kk >> 1) & 3;
            const int which = kk >> 3;
            const int pack = kk & 1;
            const int widx = tigw * 72 + pr * 32 + gd * 4 + ntl * 2 + which;
            __nv_bfloat16 hv = __float2bfloat16(b_pref[i]);
            reinterpret_cast<unsigned short*>(&Bs[buf][0][wn][widx])[pack] =
                *reinterpret_cast<unsigned short*>(&hv);
            if (SPLIT) {
                float lo = b_pref[i] - __bfloat162float(hv);
                __nv_bfloat16 lv = __float2bfloat16(lo);
                reinterpret_cast<unsigned short*>(&Bs[buf][NSP-1][wn][widx])[pack] =
                    *reinterpret_cast<unsigned short*>(&lv);
            }
        }
    };

    load_gmem(0);
    store_smem(0);
    __syncthreads();

    int buf = 0;
    const int mb0 = wm >> 4;   // 0,2,4,6

    for (int k0 = 0; k0 < K; k0 += BK) {
        const bool more = (k0 + BK) < K;
        if (more) load_gmem(k0 + BK);

        unsigned afr[NSP][2][4];
        uint4 bfr[NSP][2];
#pragma unroll
        for (int s = 0; s < NSP; s++) {
#pragma unroll
            for (int mt = 0; mt < 2; mt++) {
                uint4 av = *reinterpret_cast<const uint4*>(&As[buf][s][mb0 + mt][lane][0]);
                afr[s][mt][0] = av.x; afr[s][mt][1] = av.y;
                afr[s][mt][2] = av.z; afr[s][mt][3] = av.w;
            }
#pragma unroll
            for (int pr = 0; pr < 2; pr++)
                bfr[s][pr] = *reinterpret_cast<const uint4*>(
                    &Bs[buf][s][wn2][tig * 72 + pr * 32 + gid * 4]);
        }
#pragma unroll
        for (int mt = 0; mt < 2; mt++)
#pragma unroll
            for (int pr = 0; pr < 2; pr++) {
                mma_bf16(acc[mt][2*pr],   afr[0][mt], bfr[0][pr].x, bfr[0][pr].y);
                mma_bf16(acc[mt][2*pr+1], afr[0][mt], bfr[0][pr].z, bfr[0][pr].w);
                if (SPLIT) {
                    mma_bf16(acc[mt][2*pr],   afr[0][mt], bfr[NSP-1][pr].x, bfr[NSP-1][pr].y);
                    mma_bf16(acc[mt][2*pr+1], afr[0][mt], bfr[NSP-1][pr].z, bfr[NSP-1][pr].w);
                    mma_bf16(acc[mt][2*pr],   afr[NSP-1][mt], bfr[0][pr].x, bfr[0][pr].y);
                    mma_bf16(acc[mt][2*pr+1], afr[NSP-1][mt], bfr[0][pr].z, bfr[0][pr].w);
                }
            }

        if (more) store_smem(buf ^ 1);
        __syncthreads();
        buf ^= 1;
    }

    // Epilogue
#pragma unroll
    for (int mt = 0; mt < 2; mt++) {
        int row0 = bm + wm + mt * 16 + gid;
#pragma unroll
        for (int nt = 0; nt < 4; nt++) {
            int col0 = bn + wn2 * 32 + nt * 8 + 2 * tig;
            if (col0 < N) {
                C[(size_t)row0 * N + col0]       = acc[mt][nt][0] + bias[col0];
                C[(size_t)(row0 + 8) * N + col0] = acc[mt][nt][2] + bias[col0];
            }
            if (col0 + 1 < N) {
                C[(size_t)row0 * N + col0 + 1]       = acc[mt][nt][1] + bias[col0 + 1];
                C[(size_t)(row0 + 8) * N + col0 + 1] = acc[mt][nt][3] + bias[col0 + 1];
            }
        }
    }
}

// ---------------------------------------------------------------------------
// Weight fusion (exact fp32): W_f = w_pw @ [w_off | w_mask], bias_f likewise.
// ---------------------------------------------------------------------------
__global__ void fuse_weights(const float* __restrict__ wpw,
                             const float* __restrict__ woff,
                             const float* __restrict__ wmask,
                             float* __restrict__ wf)
{
    int i = blockIdx.x;
    int n = threadIdx.x;
    if (n >= NFUS) return;
    const float* wrow = wpw + (size_t)i * Cc;
    float acc = 0.f;
    if (n < 108) {
        for (int o = 0; o < Cc; o++) acc = fmaf(wrow[o], woff[(size_t)o * 108 + n], acc);
    } else {
        int n2 = n - 108;
        for (int o = 0; o < Cc; o++) acc = fmaf(wrow[o], wmask[(size_t)o * 54 + n2], acc);
    }
    wf[(size_t)i * NFUS + n] = acc;
}

__global__ void fuse_bias(const float* __restrict__ bpw,
                          const float* __restrict__ woff,
                          const float* __restrict__ wmask,
                          const float* __restrict__ boff,
                          const float* __restrict__ bmask,
                          float* __restrict__ bf)
{
    int n = threadIdx.x;
    if (n >= NFUS) return;
    float acc = (n < 108) ? boff[n] : bmask[n - 108];
    if (n < 108) {
        for (int o = 0; o < Cc; o++) acc = fmaf(bpw[o], woff[(size_t)o * 108 + n], acc);
    } else {
        int n2 = n - 108;
        for (int o = 0; o < Cc; o++) acc = fmaf(bpw[o], wmask[(size_t)o * 54 + n2], acc);
    }
    bf[n] = acc;
}

// ---------------------------------------------------------------------------
// Depthwise 3x3 + bias + SiLU, register-blocked: each thread computes a
// 4-pixel row run x 4 channels (18 float4 loads -> 4 outputs).
// ---------------------------------------------------------------------------
__global__ __launch_bounds__(256) void dw_silu(
    const float4* __restrict__ x, const float4* __restrict__ wdw,
    const float4* __restrict__ bdw, float4* __restrict__ out)
{
    const int C4 = Cc / 4;        // 48
    const int RW = Wd / 4;        // 32 runs per row
    const size_t total = (size_t)(M_PIX / 4) * C4;
    size_t idx = (size_t)blockIdx.x * blockDim.x + threadIdx.x;
    if (idx >= total) return;

    int c4 = (int)(idx % C4);
    int run = (int)(idx / C4);
    int w0 = (run % RW) * 4;
    int h = (run / RW) % Hh;
    int b = run / (RW * Hh);

    float4 bias = bdw[c4];
    float4 acc[4] = {bias, bias, bias, bias};
    const float4 z = make_float4(0.f, 0.f, 0.f, 0.f);

#pragma unroll
    for (int ky = 0; ky < 3; ky++) {
        int hy = h + ky - 1;
        if (hy < 0 || hy >= Hh) continue;
        const float4* row = x + ((size_t)(b * Hh + hy) * Wd) * C4 + c4;
        float4 xv[6];
        xv[0] = (w0 > 0) ? row[(size_t)(w0 - 1) * C4] : z;
#pragma unroll
        for (int t = 0; t < 4; t++) xv[1 + t] = row[(size_t)(w0 + t) * C4];
        xv[5] = (w0 + 4 < Wd) ? row[(size_t)(w0 + 4) * C4] : z;

        float4 wt[3];
#pragma unroll
        for (int kx = 0; kx < 3; kx++) wt[kx] = wdw[(ky * 3 + kx) * C4 + c4];

#pragma unroll
        for (int ow = 0; ow < 4; ow++) {
#pragma unroll
            for (int kx = 0; kx < 3; kx++) {
                float4 v = xv[ow + kx];
                acc[ow].x = fmaf(v.x, wt[kx].x, acc[ow].x);
                acc[ow].y = fmaf(v.y, wt[kx].y, acc[ow].y);
                acc[ow].z = fmaf(v.z, wt[kx].z, acc[ow].z);
                acc[ow].w = fmaf(v.w, wt[kx].w, acc[ow].w);
            }
        }
    }

    float4* orow = out + ((size_t)(b * Hh + h) * Wd) * C4 + c4;
#pragma unroll
    for (int ow = 0; ow < 4; ow++) {
        float4 a = acc[ow];
        a.x = a.x / (1.f + expf(-a.x));
        a.y = a.y / (1.f + expf(-a.y));
        a.z = a.z / (1.f + expf(-a.z));
        a.w = a.w / (1.f + expf(-a.w));
        orow[(size_t)(w0 + ow) * C4] = a;
    }
}

// ---------------------------------------------------------------------------
// Tiled deformable sampling + softmax (unchanged from round 3).
// ---------------------------------------------------------------------------
__global__ __launch_bounds__(256) void deform_tile(
    const float* __restrict__ xproj, const float* __restrict__ offmsk,
    float* __restrict__ out)
{
    const int tile = blockIdx.x;
    const int g = blockIdx.y;
    const int tid = threadIdx.x;

    const int b  = tile >> 8;
    const int ty = (tile >> 4) & 15;
    const int tx = tile & 15;
    const int h0 = ty * 8, w0 = tx * 8;

    __shared__ float2 xs[13 * 13 * 16];
    __shared__ float s_ph[64][KK2], s_pw[64][KK2], s_a[64][KK2];

    for (int idx = tid; idx < 13 * 13 * 8; idx += 256) {
        int cell = idx >> 3;
        int c4 = idx & 7;
        int hi = cell / 13, wi = cell % 13;
        int row = min(max(h0 - 2 + hi, 0), Hh - 1);
        int col = min(max(w0 - 2 + wi, 0), Wd - 1);
        float4 v = *reinterpret_cast<const float4*>(
            &xproj[(((size_t)(b * Hh + row)) * Wd + col) * Cc + g * GC + c4 * 4]);
        xs[cell * 16 + c4 * 2]     = make_float2(v.x, v.y);
        xs[cell * 16 + c4 * 2 + 1] = make_float2(v.z, v.w);
    }

    if (tid < 64) {
        int py = tid >> 3, px = tid & 7;
        int h = h0 + py, w = w0 + px;
        const float* om = offmsk + (((size_t)(b * Hh + h)) * Wd + w) * NFUS;
        float m[KK2], mx = -1e30f;
#pragma unroll
        for (int k = 0; k < KK2; k++) { m[k] = om[108 + g * KK2 + k]; mx = fmaxf(mx, m[k]); }
        float sum = 0.f;
#pragma unroll
        for (int k = 0; k < KK2; k++) { m[k] = expf(m[k] - mx); sum += m[k]; }
        float inv = 1.f / sum;
#pragma unroll
        for (int k = 0; k < KK2; k++) {
            float ph = (float)h + (float)(k / 3 - 1) + om[g * 18 + 2 * k]     * 0.1f;
            float pw = (float)w + (float)(k % 3 - 1) + om[g * 18 + 2 * k + 1] * 0.1f;
            s_ph[tid][k] = fminf(fmaxf(ph, 0.f), (float)(Hh - 1));
            s_pw[tid][k] = fminf(fmaxf(pw, 0.f), (float)(Wd - 1));
            s_a[tid][k] = m[k] * inv;
        }
    }
    __syncthreads();

    const int wid = tid >> 5;
    const int lane = tid & 31;
    const int half = lane >> 4;
    const int ch = lane & 15;

#pragma unroll
    for (int pass = 0; pass < 4; pass++) {
        int p = wid * 8 + pass * 2 + half;
        float2 acc = make_float2(0.f, 0.f);
#pragma unroll
        for (int k = 0; k < KK2; k++) {
            float ph = s_ph[p][k];
            float pw = s_pw[p][k];
            float a  = s_a [p][k];
            int hf = (int)ph;
            int wf = (int)pw;
            float fh = ph - (float)hf;
            float fw = pw - (float)wf;
            int hl = min(max(hf - (h0 - 2), 0), 11);
            int wl = min(max(wf - (w0 - 2), 0), 11);
            int c00 = (hl * 13 + wl) * 16 + ch;
            float2 v00 = xs[c00];
            float2 v01 = xs[c00 + 16];
            float2 v10 = xs[c00 + 13 * 16];
            float2 v11 = xs[c00 + 13 * 16 + 16];
            float tx0 = fmaf(fw, v01.x - v00.x, v00.x);
            float bx0 = fmaf(fw, v11.x - v10.x, v10.x);
            float ty0 = fmaf(fw, v01.y - v00.y, v00.y);
            float by0 = fmaf(fw, v11.y - v10.y, v10.y);
            acc.x = fmaf(a, fmaf(fh, bx0 - tx0, tx0), acc.x);
            acc.y = fmaf(a, fmaf(fh, by0 - ty0, ty0), acc.y);
        }
        int h = h0 + (p >> 3), w = w0 + (p & 7);
        *reinterpret_cast<float2*>(
            &out[(((size_t)(b * Hh + h)) * Wd + w) * Cc + g * GC + ch * 2]) = acc;
    }
}

// ---------------------------------------------------------------------------
// Launch
// ---------------------------------------------------------------------------
extern "C" void kernel_launch(void* const* d_in, const int* in_sizes, int n_in,
                              void* d_out, int out_size)
{
    const float* x      = (const float*)d_in[0];
    const float* w_in   = (const float*)d_in[1];
    const float* b_in   = (const float*)d_in[2];
    const float* w_dw   = (const float*)d_in[3];
    const float* b_dw   = (const float*)d_in[4];
    const float* w_pw   = (const float*)d_in[5];
    const float* b_pw   = (const float*)d_in[6];
    const float* w_off  = (const float*)d_in[7];
    const float* b_off  = (const float*)d_in[8];
    const float* w_mask = (const float*)d_in[9];
    const float* b_mask = (const float*)d_in[10];
    const float* w_out  = (const float*)d_in[11];
    const float* b_out  = (const float*)d_in[12];
    float* out = (float*)d_out;

    float *xproj, *tmp, *offmsk, *wf, *bf;
    cudaGetSymbolAddress((void**)&xproj,  g_xproj);
    cudaGetSymbolAddress((void**)&tmp,    g_tmp);
    cudaGetSymbolAddress((void**)&offmsk, g_offmsk);
    cudaGetSymbolAddress((void**)&wf,     g_wf);
    cudaGetSymbolAddress((void**)&bf,     g_bf);

    const int M = M_PIX, K = Cc;
    dim3 blk(256);
    dim3 grid_c(3, M / 128);   // N=192
    dim3 grid_f(3, M / 128);   // N=162

    // 0. fold pw into offset/mask projections (exact fp32)
    fuse_weights<<<Cc, 192>>>(w_pw, w_off, w_mask, wf);
    fuse_bias<<<1, 192>>>(b_pw, w_off, w_mask, b_off, b_mask, bf);
    // 1. x_proj = x @ w_in + b_in  (bf16x3)
    gemm_bf16<true><<<grid_c, blk>>>(x, w_in, b_in, xproj, M, Cc, K);
    // 2. depthwise 3x3 + SiLU -> tmp
    {
        size_t n = (size_t)(M_PIX / 4) * (Cc / 4);
        dw_silu<<<(unsigned)((n + 255) / 256), 256>>>(
            (const float4*)x, (const float4*)w_dw, (const float4*)b_dw, (float4*)tmp);
    }
    // 3. [offsets|mask] = dwout @ W_f + b_f  (plain bf16, damped path)
    gemm_bf16<false><<<grid_f, blk>>>(tmp, wf, bf, offmsk, M, NFUS, K);
    // 4. tiled softmax + deformable sampling -> tmp (reused)
    deform_tile<<<dim3(2048, Gg), 256>>>(xproj, offmsk, tmp);
    // 5. out = sampled @ w_out + b_out  (bf16x3)
    gemm_bf16<true><<<grid_c, blk>>>(tmp, w_out, b_out, out, M, Cc, K);
}